// round 4
// baseline (speedup 1.0000x reference)
#include <cuda_runtime.h>
#include <cstdint>

#define B_ 4
#define N_ 2048
#define M_ 2048
#define C_ 1024
#define H_ 16
#define D_ 64
#define SCALE_ 0.125f

// Scratch (allocation-free rule: __device__ globals)
__device__ float g_q[(size_t)B_ * H_ * N_ * D_];   // (B,H,N,D)
__device__ float g_k[(size_t)B_ * H_ * M_ * D_];   // (B,H,M,D)
__device__ float g_v[(size_t)B_ * H_ * M_ * D_];   // (B,H,M,D)
__device__ float g_x[(size_t)B_ * N_ * C_];        // (B,N,C) attention output

// ---------------------------------------------------------------------------
// helpers
// ---------------------------------------------------------------------------
__device__ __forceinline__ uint32_t f2tf(float x) {
    uint32_t u;
    asm("cvt.rna.tf32.f32 %0, %1;" : "=r"(u) : "f"(x));
    return u;
}

__device__ __forceinline__ void mma8(float c[4],
                                     uint32_t a0, uint32_t a1, uint32_t a2, uint32_t a3,
                                     uint32_t b0, uint32_t b1) {
    asm volatile(
        "mma.sync.aligned.m16n8k8.row.col.f32.tf32.tf32.f32 "
        "{%0,%1,%2,%3},{%4,%5,%6,%7},{%8,%9},{%0,%1,%2,%3};"
        : "+f"(c[0]), "+f"(c[1]), "+f"(c[2]), "+f"(c[3])
        : "r"(a0), "r"(a1), "r"(a2), "r"(a3), "r"(b0), "r"(b1));
}

// ---------------------------------------------------------------------------
// 128x128 tf32 GEMM tile (NT): out[r][c] = sum_k X[r][k] * W[c][k]
// 256 threads / 8 warps (4m x 2n), warp tile 32x64.
// BK=16, DOUBLE-BUFFERED tf32 smem (stride 20 => conflict-free everywhere),
// cvt only in the store path (16/thread/kt). ONE __syncthreads per k-step.
// Correctness of single sync: last readers of buffer b (compute kt-2) are
// behind sync(kt-1), which precedes any STS(kt) into b.
// ---------------------------------------------------------------------------
#define GSTRIDE 20
#define GSTAGE  (128 * GSTRIDE)

__device__ __forceinline__ void gemm_tile(const float* __restrict__ X,
                                          const float* __restrict__ W,
                                          int row0, int col0, float c[2][8][4]) {
    __shared__ uint32_t As[2][GSTAGE];
    __shared__ uint32_t Bs[2][GSTAGE];
    const int tid  = threadIdx.x;
    const int lane = tid & 31;
    const int g    = lane >> 2, tg = lane & 3;
    const int wid  = tid >> 5;
    const int wm   = (wid & 3) * 32;
    const int wn   = (wid >> 2) * 64;

    // Loader: threads 0..127 own A row r, threads 128..255 own B row r.
    const int r = tid & 127;
    const float* src = (tid < 128) ? (X + (size_t)(row0 + r) * C_)
                                   : (W + (size_t)(col0 + r) * C_);

    float4 pre[4];
    #pragma unroll
    for (int i = 0; i < 4; ++i) pre[i] = *(const float4*)(src + i * 4);

    for (int kt = 0; kt < C_ / 16; ++kt) {
        uint32_t* dst = (tid < 128) ? &As[kt & 1][r * GSTRIDE]
                                    : &Bs[kt & 1][r * GSTRIDE];
        #pragma unroll
        for (int i = 0; i < 4; ++i)
            *(uint4*)&dst[i * 4] = make_uint4(f2tf(pre[i].x), f2tf(pre[i].y),
                                              f2tf(pre[i].z), f2tf(pre[i].w));
        __syncthreads();
        if (kt + 1 < C_ / 16) {
            #pragma unroll
            for (int i = 0; i < 4; ++i)
                pre[i] = *(const float4*)(src + (kt + 1) * 16 + i * 4);
        }
        const uint32_t* A  = As[kt & 1];
        const uint32_t* Bb = Bs[kt & 1];
        #pragma unroll
        for (int kk = 0; kk < 2; ++kk) {
            uint32_t a[2][4];
            #pragma unroll
            for (int mt = 0; mt < 2; ++mt) {
                int ab = (wm + mt * 16 + g) * GSTRIDE + kk * 8 + tg;
                a[mt][0] = A[ab];
                a[mt][1] = A[ab + 8 * GSTRIDE];
                a[mt][2] = A[ab + 4];
                a[mt][3] = A[ab + 8 * GSTRIDE + 4];
            }
            uint32_t b[8][2];
            #pragma unroll
            for (int nt = 0; nt < 8; ++nt) {
                int bb = (wn + nt * 8 + g) * GSTRIDE + kk * 8 + tg;
                b[nt][0] = Bb[bb];
                b[nt][1] = Bb[bb + 4];
            }
            #pragma unroll
            for (int mt = 0; mt < 2; ++mt)
                #pragma unroll
                for (int nt = 0; nt < 8; ++nt)
                    mma8(c[mt][nt], a[mt][0], a[mt][1], a[mt][2], a[mt][3],
                         b[nt][0], b[nt][1]);
        }
    }
}

// ---------------------------------------------------------------------------
// QKV projections (z = 0/1/2 -> q/k/v), output scattered to (B,H,S,D)
// ---------------------------------------------------------------------------
__global__ void __launch_bounds__(256, 2) proj_qkv_kernel(
    const float* __restrict__ q_in, const float* __restrict__ k_in,
    const float* __restrict__ v_in, const float* __restrict__ Wq,
    const float* __restrict__ Wk, const float* __restrict__ Wv) {
    const float* X; const float* W; float* O;
    if (blockIdx.z == 0)      { X = q_in; W = Wq; O = g_q; }
    else if (blockIdx.z == 1) { X = k_in; W = Wk; O = g_k; }
    else                      { X = v_in; W = Wv; O = g_v; }

    const int row0 = blockIdx.y * 128;
    const int col0 = blockIdx.x * 128;

    float c[2][8][4];
    #pragma unroll
    for (int mt = 0; mt < 2; ++mt)
        #pragma unroll
        for (int nt = 0; nt < 8; ++nt)
            #pragma unroll
            for (int j = 0; j < 4; ++j) c[mt][nt][j] = 0.f;

    gemm_tile(X, W, row0, col0, c);

    const int lane = threadIdx.x & 31, wid = threadIdx.x >> 5;
    const int g = lane >> 2, tg = lane & 3;
    const int wm = (wid & 3) * 32, wn = (wid >> 2) * 64;

    #pragma unroll
    for (int mt = 0; mt < 2; ++mt)
        #pragma unroll
        for (int half = 0; half < 2; ++half) {
            int r = row0 + wm + mt * 16 + g + half * 8;
            int b = r >> 11, s = r & 2047;
            #pragma unroll
            for (int nt = 0; nt < 8; ++nt) {
                int col = col0 + wn + nt * 8 + 2 * tg;
                int h = col >> 6, d0 = col & 63;
                *(float2*)&O[((size_t)(b * H_ + h) * N_ + s) * D_ + d0] =
                    make_float2(c[mt][nt][half * 2], c[mt][nt][half * 2 + 1]);
            }
        }
}

// ---------------------------------------------------------------------------
// Output projection + bias -> d_out (B,N,C)
// ---------------------------------------------------------------------------
__global__ void __launch_bounds__(256, 2) proj_out_kernel(
    const float* __restrict__ Wp, const float* __restrict__ bp,
    float* __restrict__ out) {
    const int row0 = blockIdx.y * 128;
    const int col0 = blockIdx.x * 128;

    float c[2][8][4];
    #pragma unroll
    for (int mt = 0; mt < 2; ++mt)
        #pragma unroll
        for (int nt = 0; nt < 8; ++nt)
            #pragma unroll
            for (int j = 0; j < 4; ++j) c[mt][nt][j] = 0.f;

    gemm_tile(g_x, Wp, row0, col0, c);

    const int lane = threadIdx.x & 31, wid = threadIdx.x >> 5;
    const int g = lane >> 2, tg = lane & 3;
    const int wm = (wid & 3) * 32, wn = (wid >> 2) * 64;

    #pragma unroll
    for (int mt = 0; mt < 2; ++mt)
        #pragma unroll
        for (int half = 0; half < 2; ++half) {
            int r = row0 + wm + mt * 16 + g + half * 8;
            #pragma unroll
            for (int nt = 0; nt < 8; ++nt) {
                int col = col0 + wn + nt * 8 + 2 * tg;
                float2 bias = *(const float2*)&bp[col];
                *(float2*)&out[(size_t)r * C_ + col] =
                    make_float2(c[mt][nt][half * 2] + bias.x,
                                c[mt][nt][half * 2 + 1] + bias.y);
            }
        }
}

// ---------------------------------------------------------------------------
// Flash attention, tf32 mma, producer/consumer warps.
// 256 threads: warps 0-3 = consumers (mma + softmax, one m16 q-slab each),
// warps 4-7 = producers (LDG -> cvt -> STS of K/V, double-buffered, LDG
// issued one tile ahead). Zero cvt in consumer inner loops. 2 syncs/tile.
// smem: Kb[2][32*68] + Vb[2][32*72] tf32, Pb[64*36] tf32 = 45056 B static.
// Q staged once through the Kb region, then lives in registers (scaled tf32).
// ---------------------------------------------------------------------------
__global__ void __launch_bounds__(256, 2) flash_kernel() {
    __shared__ uint32_t Kb[2][32 * 68];
    __shared__ uint32_t Vb[2][32 * 72];
    __shared__ uint32_t Pb[64 * 36];

    const int tid  = threadIdx.x;
    const int lane = tid & 31, w = tid >> 5;
    const int g    = lane >> 2, tg = lane & 3;
    const int bh   = blockIdx.y;
    const int n0   = blockIdx.x * 64;

    const float* qb = g_q + (size_t)bh * N_ * D_ + (size_t)n0 * D_;
    const float* kb = g_k + (size_t)bh * M_ * D_;
    const float* vb = g_v + (size_t)bh * M_ * D_;

    // ---- stage Q (64x64 raw f32, stride 68) into Kb region; all 256 thr ----
    float* Qs = (float*)&Kb[0][0];         // 64*68 = 4352 = 2*(32*68) words
    {
        const int r = tid >> 2, q = tid & 3;
        const float* qp = qb + r * 64 + q * 16;
        #pragma unroll
        for (int i = 0; i < 4; ++i)
            *(float4*)&Qs[r * 68 + q * 16 + i * 4] = *(const float4*)(qp + i * 4);
    }
    __syncthreads();

    // ---- consumers extract Q fragments (scaled, tf32) into registers ----
    uint32_t qf[8][4];
    if (w < 4) {
        #pragma unroll
        for (int kk = 0; kk < 8; ++kk) {
            int ab = (w * 16 + g) * 68 + kk * 8 + tg;
            qf[kk][0] = f2tf(Qs[ab] * SCALE_);
            qf[kk][1] = f2tf(Qs[ab + 8 * 68] * SCALE_);
            qf[kk][2] = f2tf(Qs[ab + 4] * SCALE_);
            qf[kk][3] = f2tf(Qs[ab + 8 * 68 + 4] * SCALE_);
        }
    }
    __syncthreads();    // Q region free for K tiles

    float o[8][4];
    float mrow[2], lrow[2];
    #pragma unroll
    for (int nt = 0; nt < 8; ++nt)
        #pragma unroll
        for (int j = 0; j < 4; ++j) o[nt][j] = 0.f;
    mrow[0] = mrow[1] = -1e30f;
    lrow[0] = lrow[1] = 0.f;

    // producer-local state
    const int tid2 = tid - 128;                 // valid for w>=4
    const int pr = tid2 & 31, pq = tid2 >> 5;   // row 0..31, quarter 0..3
    float4 preK[4], preV[4];

    if (w >= 4) {
        // LDG tile 0 into regs; STS into buf0; LDG tile 1.
        const float* ks = kb + (size_t)pr * 64 + pq * 16;
        const float* vs = vb + (size_t)pr * 64 + pq * 16;
        #pragma unroll
        for (int i = 0; i < 4; ++i) { preK[i] = *(const float4*)(ks + i * 4);
                                      preV[i] = *(const float4*)(vs + i * 4); }
        #pragma unroll
        for (int i = 0; i < 4; ++i) {
            *(uint4*)&Kb[0][pr * 68 + pq * 16 + i * 4] =
                make_uint4(f2tf(preK[i].x), f2tf(preK[i].y), f2tf(preK[i].z), f2tf(preK[i].w));
            *(uint4*)&Vb[0][pr * 72 + pq * 16 + i * 4] =
                make_uint4(f2tf(preV[i].x), f2tf(preV[i].y), f2tf(preV[i].z), f2tf(preV[i].w));
        }
        #pragma unroll
        for (int i = 0; i < 4; ++i) { preK[i] = *(const float4*)(ks + 32 * 64 + i * 4);
                                      preV[i] = *(const float4*)(vs + 32 * 64 + i * 4); }
    }
    __syncthreads();    // buf0 ready

    for (int t = 0; t < M_ / 32; ++t) {
        const uint32_t* K = Kb[t & 1];
        const uint32_t* V = Vb[t & 1];

        if (w < 4) {
            // ---- S = (Q*SCALE) K^T : m16 x n32 x k64 per warp ----
            float s[4][4];
            #pragma unroll
            for (int nt = 0; nt < 4; ++nt)
                #pragma unroll
                for (int j = 0; j < 4; ++j) s[nt][j] = 0.f;

            #pragma unroll
            for (int kk = 0; kk < 8; ++kk) {
                #pragma unroll
                for (int nt = 0; nt < 4; ++nt) {
                    int bb = (nt * 8 + g) * 68 + kk * 8 + tg;
                    mma8(s[nt], qf[kk][0], qf[kk][1], qf[kk][2], qf[kk][3],
                         K[bb], K[bb + 4]);
                }
            }

            // ---- online softmax (reduce over tg lanes) ----
            #pragma unroll
            for (int r = 0; r < 2; ++r) {
                float mt_ = s[0][2 * r];
                #pragma unroll
                for (int nt = 0; nt < 4; ++nt) {
                    mt_ = fmaxf(mt_, s[nt][2 * r]);
                    mt_ = fmaxf(mt_, s[nt][2 * r + 1]);
                }
                mt_ = fmaxf(mt_, __shfl_xor_sync(0xffffffffu, mt_, 1));
                mt_ = fmaxf(mt_, __shfl_xor_sync(0xffffffffu, mt_, 2));
                float mn = fmaxf(mrow[r], mt_);
                float alpha = __expf(mrow[r] - mn);
                mrow[r] = mn;
                float rs = 0.f;
                #pragma unroll
                for (int nt = 0; nt < 4; ++nt) {
                    s[nt][2 * r]     = __expf(s[nt][2 * r] - mn);
                    s[nt][2 * r + 1] = __expf(s[nt][2 * r + 1] - mn);
                    rs += s[nt][2 * r] + s[nt][2 * r + 1];
                }
                rs += __shfl_xor_sync(0xffffffffu, rs, 1);
                rs += __shfl_xor_sync(0xffffffffu, rs, 2);
                lrow[r] = lrow[r] * alpha + rs;
                #pragma unroll
                for (int nt = 0; nt < 8; ++nt) {
                    o[nt][2 * r]     *= alpha;
                    o[nt][2 * r + 1] *= alpha;
                }
            }

            // ---- store P tile [64][36] (tf32) ----
            #pragma unroll
            for (int r = 0; r < 2; ++r) {
                int prow = w * 16 + g + 8 * r;
                #pragma unroll
                for (int nt = 0; nt < 4; ++nt)
                    *(uint2*)&Pb[prow * 36 + nt * 8 + 2 * tg] =
                        make_uint2(f2tf(s[nt][2 * r]), f2tf(s[nt][2 * r + 1]));
            }
        } else {
            // ---- producers: STS tile t+1 (regs), LDG tile t+2 ----
            if (t + 1 < M_ / 32) {
                uint32_t* Kd = &Kb[(t + 1) & 1][pr * 68 + pq * 16];
                uint32_t* Vd = &Vb[(t + 1) & 1][pr * 72 + pq * 16];
                #pragma unroll
                for (int i = 0; i < 4; ++i) {
                    Kd[i * 4 + 0] = f2tf(preK[i].x); Kd[i * 4 + 1] = f2tf(preK[i].y);
                    Kd[i * 4 + 2] = f2tf(preK[i].z); Kd[i * 4 + 3] = f2tf(preK[i].w);
                    Vd[i * 4 + 0] = f2tf(preV[i].x); Vd[i * 4 + 1] = f2tf(preV[i].y);
                    Vd[i * 4 + 2] = f2tf(preV[i].z); Vd[i * 4 + 3] = f2tf(preV[i].w);
                }
                if (t + 2 < M_ / 32) {
                    const float* ks = kb + (size_t)((t + 2) * 32 + pr) * 64 + pq * 16;
                    const float* vs = vb + (size_t)((t + 2) * 32 + pr) * 64 + pq * 16;
                    #pragma unroll
                    for (int i = 0; i < 4; ++i) { preK[i] = *(const float4*)(ks + i * 4);
                                                  preV[i] = *(const float4*)(vs + i * 4); }
                }
            }
        }
        __syncthreads();   // P ready; tile t+1 ready

        if (w < 4) {
            // ---- O += P V : m16 x n64 x k32 per warp ----
            #pragma unroll
            for (int kk = 0; kk < 4; ++kk) {
                int ab = (w * 16 + g) * 36 + kk * 8 + tg;
                uint32_t a0 = Pb[ab], a1 = Pb[ab + 8 * 36];
                uint32_t a2 = Pb[ab + 4], a3 = Pb[ab + 8 * 36 + 4];
                #pragma unroll
                for (int nt = 0; nt < 8; ++nt) {
                    uint32_t b0 = V[(kk * 8 + tg) * 72 + nt * 8 + g];
                    uint32_t b1 = V[(kk * 8 + tg + 4) * 72 + nt * 8 + g];
                    mma8(o[nt], a0, a1, a2, a3, b0, b1);
                }
            }
        }
        __syncthreads();   // PV(t) done: P and Vb[t&1] may be overwritten
    }

    // ---- normalize + write (B,N,C) ----
    if (w < 4) {
        const int b = bh >> 4, h = bh & 15;
        #pragma unroll
        for (int r = 0; r < 2; ++r) {
            float inv = 1.0f / lrow[r];
            int qrow = n0 + w * 16 + g + 8 * r;
            #pragma unroll
            for (int nt = 0; nt < 8; ++nt) {
                *(float2*)&g_x[(size_t)(b * N_ + qrow) * C_ + h * 64 + nt * 8 + 2 * tg] =
                    make_float2(o[nt][2 * r] * inv, o[nt][2 * r + 1] * inv);
            }
        }
    }
}

// ---------------------------------------------------------------------------
extern "C" void kernel_launch(void* const* d_in, const int* in_sizes, int n_in,
                              void* d_out, int out_size) {
    const float* query = (const float*)d_in[0];
    const float* key   = (const float*)d_in[1];
    const float* value = (const float*)d_in[2];
    const float* Wq    = (const float*)d_in[3];
    const float* Wk    = (const float*)d_in[4];
    const float* Wv    = (const float*)d_in[5];
    const float* Wp    = (const float*)d_in[6];
    const float* bp    = (const float*)d_in[7];
    float* out = (float*)d_out;

    dim3 gqkv(C_ / 128, (B_ * N_) / 128, 3);
    proj_qkv_kernel<<<gqkv, 256>>>(query, key, value, Wq, Wk, Wv);

    dim3 gfl(N_ / 64, B_ * H_);
    flash_kernel<<<gfl, 256>>>();

    dim3 gout(C_ / 128, (B_ * N_) / 128);
    proj_out_kernel<<<gout, 256>>>(Wp, bp, out);
}

// round 7
// speedup vs baseline: 2.0101x; 2.0101x over previous
#include <cuda_runtime.h>
#include <cuda_fp16.h>
#include <cstdint>

#define B_ 4
#define N_ 2048
#define M_ 2048
#define C_ 1024
#define H_ 16
#define D_ 64
#define SCALE_ 0.125f

// Scratch (allocation-free rule: __device__ globals)
__device__ float g_q[(size_t)B_ * H_ * N_ * D_];   // (B,H,N,D)
__device__ float g_k[(size_t)B_ * H_ * M_ * D_];   // (B,H,M,D)
__device__ float g_v[(size_t)B_ * H_ * M_ * D_];   // (B,H,M,D)
__device__ float g_x[(size_t)B_ * N_ * C_];        // (B,N,C) attention output

// ---------------------------------------------------------------------------
// helpers
// ---------------------------------------------------------------------------
__device__ __forceinline__ uint32_t pkh2(float x, float y) {
    __half2 h = __floats2half2_rn(x, y);   // lo = x (even k), hi = y
    return *(uint32_t*)&h;
}

// m16n8k16 fp16 mma, fp32 accumulate.
// A frag: a0=(row g, k 2tg..2tg+1) a1=(g+8, same) a2=(g, k 8+2tg..) a3=(g+8, ..)
// B frag: b0=(k 2tg.., col g) b1=(k 8+2tg.., col g)
// C frag: c0,c1=(g, 2tg),(g, 2tg+1); c2,c3=(g+8, ...)
__device__ __forceinline__ void mma16(float c[4],
                                      uint32_t a0, uint32_t a1, uint32_t a2, uint32_t a3,
                                      uint32_t b0, uint32_t b1) {
    asm volatile(
        "mma.sync.aligned.m16n8k16.row.col.f32.f16.f16.f32 "
        "{%0,%1,%2,%3},{%4,%5,%6,%7},{%8,%9},{%0,%1,%2,%3};"
        : "+f"(c[0]), "+f"(c[1]), "+f"(c[2]), "+f"(c[3])
        : "r"(a0), "r"(a1), "r"(a2), "r"(a3), "r"(b0), "r"(b1));
}

// ---------------------------------------------------------------------------
// 128x128 fp16 GEMM tile (NT): out[r][c] = sum_k X[r][k] * W[c][k]
// 256 threads / 8 warps (4m x 2n), warp tile 32x64. BK=32.
// smem rows = 16 half2 + pad 4 -> stride 20 (20g mod 32 distinct => frag
// loads conflict-free). Structure identical to the round-2 tf32 kernel that
// reached the HMMA ceiling; mma instruction count halved via k16.
// ---------------------------------------------------------------------------
#define GS 20

__device__ __forceinline__ void gemm_tile(const float* __restrict__ X,
                                          const float* __restrict__ W,
                                          int row0, int col0, float c[2][8][4]) {
    __shared__ uint32_t As[128 * GS];
    __shared__ uint32_t Bs[128 * GS];
    const int tid  = threadIdx.x;
    const int lane = tid & 31;
    const int g    = lane >> 2, tg = lane & 3;
    const int wid  = tid >> 5;
    const int wm   = (wid & 3) * 32;
    const int wn   = (wid >> 2) * 64;

    const float4* Xg = (const float4*)X;
    const float4* Wg = (const float4*)W;

    int rA[4], c4[4];
    float4 pa[4], pb[4];
    #pragma unroll
    for (int i = 0; i < 4; ++i) {
        int idx = tid + i * 256;
        rA[i] = idx >> 3;
        c4[i] = idx & 7;
        pa[i] = Xg[(size_t)(row0 + rA[i]) * (C_ / 4) + c4[i]];
        pb[i] = Wg[(size_t)(col0 + rA[i]) * (C_ / 4) + c4[i]];
    }

    for (int kt = 0; kt < C_ / 32; ++kt) {
        #pragma unroll
        for (int i = 0; i < 4; ++i) {
            *(uint2*)&As[rA[i] * GS + c4[i] * 2] =
                make_uint2(pkh2(pa[i].x, pa[i].y), pkh2(pa[i].z, pa[i].w));
            *(uint2*)&Bs[rA[i] * GS + c4[i] * 2] =
                make_uint2(pkh2(pb[i].x, pb[i].y), pkh2(pb[i].z, pb[i].w));
        }
        __syncthreads();
        if (kt + 1 < C_ / 32) {
            #pragma unroll
            for (int i = 0; i < 4; ++i) {
                pa[i] = Xg[(size_t)(row0 + rA[i]) * (C_ / 4) + (kt + 1) * 8 + c4[i]];
                pb[i] = Wg[(size_t)(col0 + rA[i]) * (C_ / 4) + (kt + 1) * 8 + c4[i]];
            }
        }
        #pragma unroll
        for (int kk = 0; kk < 2; ++kk) {           // two k16 steps per BK=32
            uint32_t a[2][4];
            #pragma unroll
            for (int mt = 0; mt < 2; ++mt) {
                int ab = (wm + mt * 16 + g) * GS + kk * 8 + tg;
                a[mt][0] = As[ab];
                a[mt][1] = As[ab + 8 * GS];
                a[mt][2] = As[ab + 4];
                a[mt][3] = As[ab + 8 * GS + 4];
            }
            uint32_t b[8][2];
            #pragma unroll
            for (int nt = 0; nt < 8; ++nt) {
                int bb = (wn + nt * 8 + g) * GS + kk * 8 + tg;
                b[nt][0] = Bs[bb];
                b[nt][1] = Bs[bb + 4];
            }
            #pragma unroll
            for (int mt = 0; mt < 2; ++mt)
                #pragma unroll
                for (int nt = 0; nt < 8; ++nt)
                    mma16(c[mt][nt], a[mt][0], a[mt][1], a[mt][2], a[mt][3],
                          b[nt][0], b[nt][1]);
        }
        __syncthreads();
    }
}

// ---------------------------------------------------------------------------
// QKV projections (z = 0/1/2 -> q/k/v), output scattered to (B,H,S,D)
// ---------------------------------------------------------------------------
__global__ void __launch_bounds__(256, 1) proj_qkv_kernel(
    const float* __restrict__ q_in, const float* __restrict__ k_in,
    const float* __restrict__ v_in, const float* __restrict__ Wq,
    const float* __restrict__ Wk, const float* __restrict__ Wv) {
    const float* X; const float* W; float* O;
    if (blockIdx.z == 0)      { X = q_in; W = Wq; O = g_q; }
    else if (blockIdx.z == 1) { X = k_in; W = Wk; O = g_k; }
    else                      { X = v_in; W = Wv; O = g_v; }

    const int row0 = blockIdx.y * 128;
    const int col0 = blockIdx.x * 128;

    float c[2][8][4];
    #pragma unroll
    for (int mt = 0; mt < 2; ++mt)
        #pragma unroll
        for (int nt = 0; nt < 8; ++nt)
            #pragma unroll
            for (int j = 0; j < 4; ++j) c[mt][nt][j] = 0.f;

    gemm_tile(X, W, row0, col0, c);

    const int lane = threadIdx.x & 31, wid = threadIdx.x >> 5;
    const int g = lane >> 2, tg = lane & 3;
    const int wm = (wid & 3) * 32, wn = (wid >> 2) * 64;

    #pragma unroll
    for (int mt = 0; mt < 2; ++mt)
        #pragma unroll
        for (int half = 0; half < 2; ++half) {
            int r = row0 + wm + mt * 16 + g + half * 8;
            int b = r >> 11, s = r & 2047;
            #pragma unroll
            for (int nt = 0; nt < 8; ++nt) {
                int col = col0 + wn + nt * 8 + 2 * tg;
                int h = col >> 6, d0 = col & 63;
                *(float2*)&O[((size_t)(b * H_ + h) * N_ + s) * D_ + d0] =
                    make_float2(c[mt][nt][half * 2], c[mt][nt][half * 2 + 1]);
            }
        }
}

// ---------------------------------------------------------------------------
// Output projection + bias -> d_out (B,N,C)
// ---------------------------------------------------------------------------
__global__ void __launch_bounds__(256, 1) proj_out_kernel(
    const float* __restrict__ Wp, const float* __restrict__ bp,
    float* __restrict__ out) {
    const int row0 = blockIdx.y * 128;
    const int col0 = blockIdx.x * 128;

    float c[2][8][4];
    #pragma unroll
    for (int mt = 0; mt < 2; ++mt)
        #pragma unroll
        for (int nt = 0; nt < 8; ++nt)
            #pragma unroll
            for (int j = 0; j < 4; ++j) c[mt][nt][j] = 0.f;

    gemm_tile(g_x, Wp, row0, col0, c);

    const int lane = threadIdx.x & 31, wid = threadIdx.x >> 5;
    const int g = lane >> 2, tg = lane & 3;
    const int wm = (wid & 3) * 32, wn = (wid >> 2) * 64;

    #pragma unroll
    for (int mt = 0; mt < 2; ++mt)
        #pragma unroll
        for (int half = 0; half < 2; ++half) {
            int r = row0 + wm + mt * 16 + g + half * 8;
            #pragma unroll
            for (int nt = 0; nt < 8; ++nt) {
                int col = col0 + wn + nt * 8 + 2 * tg;
                float2 bias = *(const float2*)&bp[col];
                *(float2*)&out[(size_t)r * C_ + col] =
                    make_float2(c[mt][nt][half * 2] + bias.x,
                                c[mt][nt][half * 2 + 1] + bias.y);
            }
        }
}

// ---------------------------------------------------------------------------
// Flash attention, fp16 mma (m16n8k16), fp32 softmax/accumulators.
// 128 threads / 4 warps; block = 64 query rows of one (b,h); key tile = 32.
// Layouts (uint32 = half2):
//   Qs2[64][36]  Q natural, half2 pairs along d (A operand; pre-scaled)
//   Ks2[32][36]  K natural, half2 pairs along d (B operand for S)
//   Vt2[64][36]  V TRANSPOSED: [d][m-pair] (B operand for PV)
//   Ps2[64][20]  P [q][m-pair] (A operand for PV; own-warp rows only)
// All fragment LDS conflict-free (stride*g mod 32 spans 8 distinct offsets).
// 2 __syncthreads per tile.  28160 B static smem, 4 blocks/SM.
// ---------------------------------------------------------------------------
__global__ void __launch_bounds__(128, 4) flash_kernel() {
    __shared__ uint32_t Qs2[64 * 36];
    __shared__ uint32_t Ks2[32 * 36];
    __shared__ uint32_t Vt2[64 * 36];
    __shared__ uint32_t Ps2[64 * 20];

    const int tid  = threadIdx.x;
    const int lane = tid & 31, w = tid >> 5;
    const int g    = lane >> 2, tg = lane & 3;
    const int bh   = blockIdx.y;
    const int n0   = blockIdx.x * 64;

    const float4* qb = (const float4*)(g_q + (size_t)bh * N_ * D_);
    const float4* kb = (const float4*)(g_k + (size_t)bh * M_ * D_);
    const float4* vb = (const float4*)(g_v + (size_t)bh * M_ * D_);

    // ---- load Q tile (pre-scaled), natural layout, half2 along d ----
    #pragma unroll
    for (int i = 0; i < 8; ++i) {
        int idx = tid + i * 128;
        int r = idx >> 4, c4 = idx & 15;
        float4 v = qb[(size_t)(n0 + r) * 16 + c4];
        *(uint2*)&Qs2[r * 36 + c4 * 2] =
            make_uint2(pkh2(v.x * SCALE_, v.y * SCALE_),
                       pkh2(v.z * SCALE_, v.w * SCALE_));
    }

    float o[8][4];
    float mrow[2], lrow[2];
    #pragma unroll
    for (int nt = 0; nt < 8; ++nt)
        #pragma unroll
        for (int j = 0; j < 4; ++j) o[nt][j] = 0.f;
    mrow[0] = mrow[1] = -1e30f;
    lrow[0] = lrow[1] = 0.f;

    // K loader mapping: 512 float4 chunks / 128 thr = 4 each (natural)
    int rK[4], cK[4];
    float4 pk[4];
    #pragma unroll
    for (int i = 0; i < 4; ++i) {
        int idx = tid + i * 128;
        rK[i] = idx >> 4;
        cK[i] = idx & 15;
        pk[i] = kb[(size_t)rK[i] * 16 + cK[i]];
    }
    // V loader mapping (transpose producer): thread -> (m0=2*mi, d0=dq*8)
    const int mi = tid & 15, dq = tid >> 4;
    const int d0 = dq * 8;
    float4 pv[4];
    pv[0] = vb[(size_t)(2 * mi) * 16 + dq * 2];
    pv[1] = vb[(size_t)(2 * mi) * 16 + dq * 2 + 1];
    pv[2] = vb[(size_t)(2 * mi + 1) * 16 + dq * 2];
    pv[3] = vb[(size_t)(2 * mi + 1) * 16 + dq * 2 + 1];

    for (int t = 0; t < M_ / 32; ++t) {
        // ---- store K (natural) + V (transposed, m-pairs) tiles ----
        #pragma unroll
        for (int i = 0; i < 4; ++i)
            *(uint2*)&Ks2[rK[i] * 36 + cK[i] * 2] =
                make_uint2(pkh2(pk[i].x, pk[i].y), pkh2(pk[i].z, pk[i].w));
        {
            const float* f0 = (const float*)&pv[0];
            const float* f1 = (const float*)&pv[1];
            const float* f2 = (const float*)&pv[2];
            const float* f3 = (const float*)&pv[3];
            #pragma unroll
            for (int j = 0; j < 4; ++j) {
                Vt2[(d0 + j) * 36 + mi]     = pkh2(f0[j], f2[j]);
                Vt2[(d0 + 4 + j) * 36 + mi] = pkh2(f1[j], f3[j]);
            }
        }
        __syncthreads();

        // prefetch next tile
        if (t + 1 < M_ / 32) {
            const float4* kn = kb + (size_t)(t + 1) * 32 * 16;
            const float4* vn = vb + (size_t)(t + 1) * 32 * 16;
            #pragma unroll
            for (int i = 0; i < 4; ++i) pk[i] = kn[(size_t)rK[i] * 16 + cK[i]];
            pv[0] = vn[(size_t)(2 * mi) * 16 + dq * 2];
            pv[1] = vn[(size_t)(2 * mi) * 16 + dq * 2 + 1];
            pv[2] = vn[(size_t)(2 * mi + 1) * 16 + dq * 2];
            pv[3] = vn[(size_t)(2 * mi + 1) * 16 + dq * 2 + 1];
        }

        // ---- S = (Q*SCALE) K^T : m16 x n32 x k64 per warp (16 mma16) ----
        float s[4][4];
        #pragma unroll
        for (int nt = 0; nt < 4; ++nt)
            #pragma unroll
            for (int j = 0; j < 4; ++j) s[nt][j] = 0.f;

        #pragma unroll
        for (int kk = 0; kk < 4; ++kk) {
            int ab = (w * 16 + g) * 36 + kk * 8 + tg;
            uint32_t a0 = Qs2[ab], a1 = Qs2[ab + 8 * 36];
            uint32_t a2 = Qs2[ab + 4], a3 = Qs2[ab + 8 * 36 + 4];
            #pragma unroll
            for (int nt = 0; nt < 4; ++nt) {
                int bb = (nt * 8 + g) * 36 + kk * 8 + tg;
                mma16(s[nt], a0, a1, a2, a3, Ks2[bb], Ks2[bb + 4]);
            }
        }

        // ---- online softmax (reduce over tg lanes) ----
        #pragma unroll
        for (int r = 0; r < 2; ++r) {
            float mt_ = s[0][2 * r];
            #pragma unroll
            for (int nt = 0; nt < 4; ++nt) {
                mt_ = fmaxf(mt_, s[nt][2 * r]);
                mt_ = fmaxf(mt_, s[nt][2 * r + 1]);
            }
            mt_ = fmaxf(mt_, __shfl_xor_sync(0xffffffffu, mt_, 1));
            mt_ = fmaxf(mt_, __shfl_xor_sync(0xffffffffu, mt_, 2));
            float mn = fmaxf(mrow[r], mt_);
            float alpha = __expf(mrow[r] - mn);
            mrow[r] = mn;
            float rs = 0.f;
            #pragma unroll
            for (int nt = 0; nt < 4; ++nt) {
                s[nt][2 * r]     = __expf(s[nt][2 * r] - mn);
                s[nt][2 * r + 1] = __expf(s[nt][2 * r + 1] - mn);
                rs += s[nt][2 * r] + s[nt][2 * r + 1];
            }
            rs += __shfl_xor_sync(0xffffffffu, rs, 1);
            rs += __shfl_xor_sync(0xffffffffu, rs, 2);
            lrow[r] = lrow[r] * alpha + rs;
            #pragma unroll
            for (int nt = 0; nt < 8; ++nt) {
                o[nt][2 * r]     *= alpha;
                o[nt][2 * r + 1] *= alpha;
            }
        }

        // ---- store P (fp16 pairs along m); rows owned by this warp only ----
        #pragma unroll
        for (int nt = 0; nt < 4; ++nt) {
            Ps2[(w * 16 + g) * 20 + nt * 4 + tg]     = pkh2(s[nt][0], s[nt][1]);
            Ps2[(w * 16 + 8 + g) * 20 + nt * 4 + tg] = pkh2(s[nt][2], s[nt][3]);
        }
        __syncwarp();

        // ---- O += P V : m16 x n64 x k32 per warp (16 mma16) ----
        #pragma unroll
        for (int kk = 0; kk < 2; ++kk) {
            int ab = (w * 16 + g) * 20 + kk * 8 + tg;
            uint32_t a0 = Ps2[ab], a1 = Ps2[ab + 8 * 20];
            uint32_t a2 = Ps2[ab + 4], a3 = Ps2[ab + 8 * 20 + 4];
            #pragma unroll
            for (int nt = 0; nt < 8; ++nt) {
                int bb = (nt * 8 + g) * 36 + kk * 8 + tg;
                mma16(o[nt], a0, a1, a2, a3, Vt2[bb], Vt2[bb + 4]);
            }
        }
        __syncthreads();   // all warps done with Ks2/Vt2 before next stores
    }

    // ---- normalize + write (B,N,C) ----
    const int b = bh >> 4, h = bh & 15;
    #pragma unroll
    for (int r = 0; r < 2; ++r) {
        float inv = 1.0f / lrow[r];
        int qrow = n0 + w * 16 + g + 8 * r;
        #pragma unroll
        for (int nt = 0; nt < 8; ++nt) {
            *(float2*)&g_x[(size_t)(b * N_ + qrow) * C_ + h * 64 + nt * 8 + 2 * tg] =
                make_float2(o[nt][2 * r] * inv, o[nt][2 * r + 1] * inv);
        }
    }
}

// ---------------------------------------------------------------------------
extern "C" void kernel_launch(void* const* d_in, const int* in_sizes, int n_in,
                              void* d_out, int out_size) {
    const float* query = (const float*)d_in[0];
    const float* key   = (const float*)d_in[1];
    const float* value = (const float*)d_in[2];
    const float* Wq    = (const float*)d_in[3];
    const float* Wk    = (const float*)d_in[4];
    const float* Wv    = (const float*)d_in[5];
    const float* Wp    = (const float*)d_in[6];
    const float* bp    = (const float*)d_in[7];
    float* out = (float*)d_out;

    dim3 gqkv(C_ / 128, (B_ * N_) / 128, 3);
    proj_qkv_kernel<<<gqkv, 256>>>(query, key, value, Wq, Wk, Wv);

    dim3 gfl(N_ / 64, B_ * H_);
    flash_kernel<<<gfl, 128>>>();

    dim3 gout(C_ / 128, (B_ * N_) / 128);
    proj_out_kernel<<<gout, 256>>>(Wp, bp, out);
}